// round 9
// baseline (speedup 1.0000x reference)
#include <cuda_runtime.h>
#include <cstdint>

// MVRModel MaxSim, base sm_100 (no tcgen05 on this toolchain path).
//   B=16, Q=32, E=128, N=64 docs/batch, D=512 doc tokens.
//   score[b,n] = sum_q qmask[b,q] * max_d( dmask ? q·d : MASK ), MASK-max -> 0.
//
// R8: de-burst the DRAM stream.
//  - 256 thr/CTA, 2 CTAs/SM (296 streams, 16 warps/SM).
//  - 6 buffers x 16.9KB: 5 chunks per CTA continuously in flight; chunk c+5
//    issued BEFORE compute of chunk c (single barrier per chunk).
//  - warp = (m-tile, n-octet): bq = 32 regs -> ~70 regs/thread.
//  - rolled main loop (wait_group 4 const), barrier-free 4-chunk tail.

#define MASKV (-10000.0f)

static constexpr int BB = 16, QQ = 32, EE = 128, NN = 64, DD = 512;
static constexpr int CH = 32;                  // tokens per chunk
static constexpr int NCH = DD / CH;            // 16
static constexpr int RS = 132;                 // padded row stride (floats)
static constexpr int RSB = RS * 4;             // 528 B

static constexpr unsigned BUFB = 32u * RSB;            // 16896 per buffer
static constexpr unsigned NBUF = 6;
static constexpr unsigned OFF_RED = NBUF * BUFB;       // 101376 (64 floats)
static constexpr unsigned SMEM_BYTES = OFF_RED + 256;  // 101632 -> 2 CTAs/SM

__device__ __forceinline__ uint32_t cvta_smem(const void* p) {
    uint32_t a;
    asm("{ .reg .u64 t; cvta.to.shared.u64 t, %1; cvt.u32.u64 %0, t; }" : "=r"(a) : "l"(p));
    return a;
}

__device__ __forceinline__ void cp16(uint32_t dst, const void* src) {
    asm volatile("cp.async.cg.shared.global [%0], [%1], 16;" :: "r"(dst), "l"(src) : "memory");
}

__device__ __forceinline__ uint32_t to_tf32(float x) {
    uint32_t r;
    asm("cvt.rna.tf32.f32 %0, %1;" : "=r"(r) : "f"(x));
    return r;
}

// One 32-token chunk (16KB payload): 1024 float4s / 256 threads = 4 each.
__device__ __forceinline__ void load_chunk(uint32_t bufbase, const float4* __restrict__ src,
                                           int tid) {
#pragma unroll
    for (int i = 0; i < 4; i++) {
        int idx = tid + i * 256;          // 0..1023
        int r = idx >> 5;                 // token row 0..31
        int j = idx & 31;                 // float4 col
        cp16(bufbase + (uint32_t)r * RSB + (uint32_t)j * 16u, src + idx);
    }
    asm volatile("cp.async.commit_group;" ::: "memory");
}

// Compute one chunk: warp owns (m-tile mt rows x 8 q-cols), bq preloaded.
__device__ __forceinline__ void compute_chunk(uint32_t buf, uint32_t a_lane_off,
                                              const uint32_t (&bq)[16][2],
                                              int dok0, int dok1, float (&rmax)[2]) {
    float acc[4] = {0.0f, 0.0f, 0.0f, 0.0f};
#pragma unroll
    for (int ks = 0; ks < 16; ks++) {
        uint32_t a0, a1, a2, a3;
        asm volatile("ldmatrix.sync.aligned.m8n8.x4.shared.b16 {%0,%1,%2,%3}, [%4];"
                     : "=r"(a0), "=r"(a1), "=r"(a2), "=r"(a3)
                     : "r"(buf + a_lane_off + (uint32_t)ks * 32u));
        a0 = to_tf32(__uint_as_float(a0));
        a1 = to_tf32(__uint_as_float(a1));
        a2 = to_tf32(__uint_as_float(a2));
        a3 = to_tf32(__uint_as_float(a3));
        asm volatile(
            "mma.sync.aligned.m16n8k8.row.col.f32.tf32.tf32.f32 "
            "{%0,%1,%2,%3}, {%4,%5,%6,%7}, {%8,%9}, {%0,%1,%2,%3};"
            : "+f"(acc[0]), "+f"(acc[1]), "+f"(acc[2]), "+f"(acc[3])
            : "r"(a0), "r"(a1), "r"(a2), "r"(a3), "r"(bq[ks][0]), "r"(bq[ks][1]));
    }
    // acc: c0=(r,2c), c1=(r,2c+1), c2=(r+8,2c), c3=(r+8,2c+1); r=lane>>2, c=lane&3.
    float v0 = dok0 ? acc[0] : MASKV;
    float v1 = dok0 ? acc[1] : MASKV;
    float v2 = dok1 ? acc[2] : MASKV;
    float v3 = dok1 ? acc[3] : MASKV;
    rmax[0] = fmaxf(rmax[0], fmaxf(v0, v2));
    rmax[1] = fmaxf(rmax[1], fmaxf(v1, v3));
}

__global__ void __launch_bounds__(256, 2)
mvr_maxsim_kernel(const float* __restrict__ qe, const int* __restrict__ qm,
                  const float* __restrict__ de, const int* __restrict__ dm,
                  float* __restrict__ out) {
    extern __shared__ char smem[];
    const uint32_t sb = cvta_smem(smem);
    float* red = (float*)(smem + OFF_RED);

    const int tid = threadIdx.x;
    const int wid = tid >> 5;
    const int lid = tid & 31;
    const int mt = wid & 1;               // m-tile (chunk rows mt*16..+16)
    const int nq = wid >> 1;              // n-octet (q-cols nq*8..+8)
    const int doc = blockIdx.x;           // b*64 + n
    const int b = doc >> 6;

    // ---- Prologue: Q into buf5 (group 0), chunks 0..4 (groups 1..5) ----
    const float4* qg = (const float4*)(qe + (size_t)b * QQ * EE);
#pragma unroll
    for (int i = 0; i < 4; i++) {
        int idx = tid + i * 256;          // 0..1023
        int q = idx >> 5;
        int j = idx & 31;
        cp16(sb + 5 * BUFB + (uint32_t)q * RSB + (uint32_t)j * 16u, qg + idx);
    }
    asm volatile("cp.async.commit_group;" ::: "memory");

    const float4* dg = (const float4*)(de + (size_t)doc * DD * EE);
#pragma unroll
    for (int k = 0; k < 5; k++)
        load_chunk(sb + k * BUFB, dg + k * CH * 32, tid);

    // Wait Q (chunks 0..4 still pending).
    asm volatile("cp.async.wait_group 5;" ::: "memory");
    __syncthreads();

    // Preload B fragments: bq[ks][j] = tf32(Q[n][k]),
    // n = nq*8 + lane/4, k = ks*8 + (lane%4) + j*4.
    const float* qsm = (const float*)(smem + 5 * BUFB);
    uint32_t bq[16][2];
    {
        const float* pbase = qsm + (nq * 8 + (lid >> 2)) * RS + (lid & 3);
#pragma unroll
        for (int ks = 0; ks < 16; ks++) {
            bq[ks][0] = to_tf32(pbase[ks * 8]);
            bq[ks][1] = to_tf32(pbase[ks * 8 + 4]);
        }
    }
    __syncthreads();                      // all warps done reading Q from buf5

    const uint32_t a_lane_off =
        (uint32_t)(mt * 16 + (lid & 15)) * RSB + (uint32_t)(lid >> 4) * 16u;
    const int trow_lane = (lid >> 2);

    float rmax[2] = {MASKV, MASKV};

    // ---- Main loop: chunks 0..11, 5 in flight, issue-before-compute ----
    unsigned bi = 0;                      // buffer of chunk c
    unsigned ibi = 5;                     // buffer for chunk c+5
    for (int c = 0; c < 12; ++c) {
        const int trow = c * CH + mt * 16 + trow_lane;
        const int dok0 = dm[doc * DD + trow];
        const int dok1 = dm[doc * DD + trow + 8];

        asm volatile("cp.async.wait_group 4;" ::: "memory");   // chunk c landed
        __syncthreads();
        // Buffer (c+5)%6 was consumed in iteration c-1 (barrier above covers it).
        if (c <= 10) {
            load_chunk(sb + ibi * BUFB, dg + (c + 5) * CH * 32, tid);
            ibi = (ibi == 5) ? 0 : ibi + 1;
        }
        compute_chunk(sb + bi * BUFB, a_lane_off, bq, dok0, dok1, rmax);
        bi = (bi == 5) ? 0 : bi + 1;
    }

    // ---- Tail: chunks 12..15 all resident (issued at c=7..10); no waits ----
    asm volatile("cp.async.wait_group 0;" ::: "memory");
    __syncthreads();
#pragma unroll
    for (int c = 12; c < 16; ++c) {
        const int trow = c * CH + mt * 16 + trow_lane;
        const int dok0 = dm[doc * DD + trow];
        const int dok1 = dm[doc * DD + trow + 8];
        compute_chunk(sb + (unsigned)(c % 6) * BUFB, a_lane_off, bq, dok0, dok1, rmax);
    }

    // Butterfly max over token rows (lane bits 2..4); lanes with same (lane&3)
    // then hold the column max for q-col nq*8 + (lane&3)*2 + j.
#pragma unroll
    for (int j = 0; j < 2; j++) {
        float x = rmax[j];
#pragma unroll
        for (int o = 4; o < 32; o <<= 1)
            x = fmaxf(x, __shfl_xor_sync(0xFFFFFFFFu, x, o));
        rmax[j] = x;
    }
    if (lid < 4) {
        red[wid * 8 + lid * 2 + 0] = rmax[0];
        red[wid * 8 + lid * 2 + 1] = rmax[1];
    }
    __syncthreads();

    // Final: q = tid; combine the two m-tile warps of octet q>>3, mask, sum.
    if (tid < 32) {
        const int oq = tid >> 3;          // n-octet
        const int loc = tid & 7;          // col within octet
        float m = fmaxf(red[oq * 16 + loc], red[oq * 16 + 8 + loc]);
        const int qok = qm[b * QQ + tid];
        float contrib = (qok != 0 && m != MASKV) ? m : 0.0f;
#pragma unroll
        for (int o = 16; o; o >>= 1)
            contrib += __shfl_xor_sync(0xFFFFFFFFu, contrib, o);
        if (tid == 0) out[doc] = contrib;
    }
}

extern "C" void kernel_launch(void* const* d_in, const int* in_sizes, int n_in,
                              void* d_out, int out_size) {
    (void)in_sizes; (void)n_in; (void)out_size;
    cudaFuncSetAttribute(mvr_maxsim_kernel,
                         cudaFuncAttributeMaxDynamicSharedMemorySize, SMEM_BYTES);
    mvr_maxsim_kernel<<<BB * NN, 256, SMEM_BYTES>>>(
        (const float*)d_in[0], (const int*)d_in[1],
        (const float*)d_in[2], (const int*)d_in[3],
        (float*)d_out);
}

// round 11
// speedup vs baseline: 1.9957x; 1.9957x over previous
#include <cuda_runtime.h>
#include <cstdint>

// MVRModel MaxSim, base sm_100 (no tcgen05 on this toolchain path).
//   B=16, Q=32, E=128, N=64 docs/batch, D=512 doc tokens.
//   score[b,n] = sum_q qmask[b,q] * max_d( dmask ? q·d : MASK ), MASK-max -> 0.
//
// R9: mask-aware row gather — dmask is ~Bernoulli(0.5), and masked doc tokens
// contribute MASKV regardless of their embeddings, so their 512B rows are never
// read. Compact valid token indices per doc (ballot+popc+smem atomic), then
// cp.async-gather only valid rows (512B contiguous each). Halves DRAM traffic.
// Compute structure = R7 (warp = m16 x n16, bq in regs, 3-buf pipeline); the
// dynamic chunk count uses one commit_group per iteration (empty when done) so
// wait_group stays the constant 2.

#define MASKV (-10000.0f)

static constexpr int BB = 16, QQ = 32, EE = 128, NN = 64, DD = 512;
static constexpr int CH = 32;                  // compacted tokens per chunk
static constexpr int RS = 132;                 // padded row stride (floats)
static constexpr int RSB = RS * 4;             // 528 B

static constexpr unsigned BUFB = 32u * RSB;            // 16896 per buffer
static constexpr unsigned OFF_LIST = 3 * BUFB;         // 512 u16 = 1024 B
static constexpr unsigned OFF_CNT  = OFF_LIST + 1024;  // int
static constexpr unsigned OFF_RED  = OFF_CNT + 64;     // 64 floats
static constexpr unsigned SMEM_BYTES = OFF_RED + 256;  // ~52.3KB -> 4 CTAs/SM

__device__ __forceinline__ uint32_t cvta_smem(const void* p) {
    uint32_t a;
    asm("{ .reg .u64 t; cvta.to.shared.u64 t, %1; cvt.u32.u64 %0, t; }" : "=r"(a) : "l"(p));
    return a;
}

__device__ __forceinline__ void cp16(uint32_t dst, const void* src) {
    asm volatile("cp.async.cg.shared.global [%0], [%1], 16;" :: "r"(dst), "l"(src) : "memory");
}

__device__ __forceinline__ void commit_group() {
    asm volatile("cp.async.commit_group;" ::: "memory");
}

__device__ __forceinline__ uint32_t to_tf32(float x) {
    uint32_t r;
    asm("cvt.rna.tf32.f32 %0, %1;" : "=r"(r) : "f"(x));
    return r;
}

// Gather one chunk of 32 compacted rows (512B each). 128 threads: 4 per row,
// thread covers float4 cols (t&3) + i*4 (64B contiguous per row-quad issue).
__device__ __forceinline__ void load_chunk_gather(uint32_t bufbase,
                                                  const float4* __restrict__ dg,
                                                  const uint16_t* __restrict__ list,
                                                  int c, int tid) {
    const int r = tid >> 2;               // 0..31 compacted row in chunk
    const int q = tid & 3;
    const int g = list[c * 32 + r];       // global token row (smem broadcast x4)
    const float4* src = dg + (size_t)g * 32;
    const uint32_t dst = bufbase + (uint32_t)r * RSB;
#pragma unroll
    for (int i = 0; i < 8; i++) {
        int j = q + i * 4;                // float4 col 0..31
        cp16(dst + (uint32_t)j * 16u, src + j);
    }
    commit_group();
}

// Compute one chunk: warp owns (m-tile mt: rows mt*16..+16) x (n-half nh).
__device__ __forceinline__ void compute_chunk(uint32_t buf, uint32_t a_lane_off,
                                              const uint32_t (&bq)[2][16][2],
                                              int dok0, int dok1, float (&rmax)[2][2]) {
    float acc[2][4];
#pragma unroll
    for (int nt = 0; nt < 2; nt++)
#pragma unroll
        for (int i = 0; i < 4; i++) acc[nt][i] = 0.0f;

#pragma unroll
    for (int ks = 0; ks < 16; ks++) {
        uint32_t a0, a1, a2, a3;
        asm volatile("ldmatrix.sync.aligned.m8n8.x4.shared.b16 {%0,%1,%2,%3}, [%4];"
                     : "=r"(a0), "=r"(a1), "=r"(a2), "=r"(a3)
                     : "r"(buf + a_lane_off + (uint32_t)ks * 32u));
        a0 = to_tf32(__uint_as_float(a0));
        a1 = to_tf32(__uint_as_float(a1));
        a2 = to_tf32(__uint_as_float(a2));
        a3 = to_tf32(__uint_as_float(a3));
#pragma unroll
        for (int nt = 0; nt < 2; nt++) {
            asm volatile(
                "mma.sync.aligned.m16n8k8.row.col.f32.tf32.tf32.f32 "
                "{%0,%1,%2,%3}, {%4,%5,%6,%7}, {%8,%9}, {%0,%1,%2,%3};"
                : "+f"(acc[nt][0]), "+f"(acc[nt][1]), "+f"(acc[nt][2]), "+f"(acc[nt][3])
                : "r"(a0), "r"(a1), "r"(a2), "r"(a3),
                  "r"(bq[nt][ks][0]), "r"(bq[nt][ks][1]));
        }
    }
    // acc[nt]: c0=(r,2c), c1=(r,2c+1), c2=(r+8,2c), c3=(r+8,2c+1); r=lane>>2, c=lane&3.
#pragma unroll
    for (int nt = 0; nt < 2; nt++) {
        float v0 = dok0 ? acc[nt][0] : MASKV;
        float v1 = dok0 ? acc[nt][1] : MASKV;
        float v2 = dok1 ? acc[nt][2] : MASKV;
        float v3 = dok1 ? acc[nt][3] : MASKV;
        rmax[nt][0] = fmaxf(rmax[nt][0], fmaxf(v0, v2));
        rmax[nt][1] = fmaxf(rmax[nt][1], fmaxf(v1, v3));
    }
}

__global__ void __launch_bounds__(128, 4)
mvr_maxsim_kernel(const float* __restrict__ qe, const int* __restrict__ qm,
                  const float* __restrict__ de, const int* __restrict__ dm,
                  float* __restrict__ out) {
    extern __shared__ char smem[];
    const uint32_t sb = cvta_smem(smem);
    uint16_t* list = (uint16_t*)(smem + OFF_LIST);
    int* cnt = (int*)(smem + OFF_CNT);
    float* red = (float*)(smem + OFF_RED);

    const int tid = threadIdx.x;
    const int wid = tid >> 5;
    const int lid = tid & 31;
    const int mt = wid & 1;               // m-tile (chunk rows mt*16..+16)
    const int nh = wid >> 1;              // n-half (q-cols nh*16..+16)
    const int doc = blockIdx.x;           // b*64 + n
    const int b = doc >> 6;

    // ---- Group 0: Q (32x128) into buf2 (transient) ----
    const float4* qg = (const float4*)(qe + (size_t)b * QQ * EE);
#pragma unroll
    for (int i = 0; i < 8; i++) {
        int idx = tid + i * 128;          // 0..1023
        int qrow = idx >> 5;
        int j = idx & 31;
        cp16(sb + 2 * BUFB + (uint32_t)qrow * RSB + (uint32_t)j * 16u, qg + idx);
    }
    commit_group();

    // ---- Compaction of valid doc-token indices (overlaps the Q load) ----
    if (tid == 0) *cnt = 0;
    __syncthreads();
#pragma unroll
    for (int i = 0; i < 4; i++) {
        int tok = wid * 128 + i * 32 + lid;
        int valid = dm[doc * DD + tok] != 0;
        unsigned m = __ballot_sync(0xFFFFFFFFu, valid);
        int base = 0;
        if (lid == 0) base = atomicAdd(cnt, __popc(m));
        base = __shfl_sync(0xFFFFFFFFu, base, 0);
        if (valid) list[base + __popc(m & ((1u << lid) - 1u))] = (uint16_t)tok;
    }
    __syncthreads();
    const int V = *cnt;                    // valid tokens, 0..512
    const int NC = (V + 31) >> 5;          // chunks of 32
    // pad list to a chunk multiple with index 0 (slots >= V are invalidated later)
    for (int s = V + tid; s < NC * 32; s += 128) list[s] = 0;
    __syncthreads();

    const float4* dg = (const float4*)(de + (size_t)doc * DD * EE);

    // ---- Groups 1,2: chunks 0,1 (empty groups when NC is small) ----
    if (NC > 0) load_chunk_gather(sb + 0 * BUFB, dg, list, 0, tid); else commit_group();
    if (NC > 1) load_chunk_gather(sb + 1 * BUFB, dg, list, 1, tid); else commit_group();

    // Wait Q (2 newer groups pending), then preload B fragments.
    asm volatile("cp.async.wait_group 2;" ::: "memory");
    __syncthreads();

    // bq[nt][ks][j] = tf32(Q[n][k]); n = nh*16 + nt*8 + lane/4,
    // k = ks*8 + (lane%4) + j*4.
    const float* qsm = (const float*)(smem + 2 * BUFB);
    uint32_t bq[2][16][2];
    {
        const float* pbase = qsm + (nh * 16 + (lid >> 2)) * RS + (lid & 3);
#pragma unroll
        for (int nt = 0; nt < 2; nt++)
#pragma unroll
            for (int ks = 0; ks < 16; ks++) {
                const float* p = pbase + (nt * 8) * RS + ks * 8;
                bq[nt][ks][0] = to_tf32(p[0]);
                bq[nt][ks][1] = to_tf32(p[4]);
            }
    }
    __syncthreads();                      // Q region free for chunk 2

    // Group 3: chunk 2 into buf2.
    if (NC > 2) load_chunk_gather(sb + 2 * BUFB, dg, list, 2, tid); else commit_group();

    const uint32_t a_lane_off =
        (uint32_t)(mt * 16 + (lid & 15)) * RSB + (uint32_t)(lid >> 4) * 16u;
    const int trow_lane = (lid >> 2);

    float rmax[2][2];
    rmax[0][0] = MASKV; rmax[0][1] = MASKV; rmax[1][0] = MASKV; rmax[1][1] = MASKV;

    // ---- Main loop over compacted chunks; one commit per iteration keeps
    //      group accounting constant (wait_group 2 == chunk c landed). ----
    unsigned bi = 0;
    for (int c = 0; c < NC; ++c) {
        const int slot = c * CH + mt * 16 + trow_lane;
        const int dok0 = slot < V;
        const int dok1 = slot + 8 < V;

        asm volatile("cp.async.wait_group 2;" ::: "memory");
        __syncthreads();

        compute_chunk(sb + bi * BUFB, a_lane_off, bq, dok0, dok1, rmax);

        __syncthreads();                  // all warps done reading buf bi
        if (c + 3 < NC) load_chunk_gather(sb + bi * BUFB, dg, list, c + 3, tid);
        else            commit_group();
        bi = (bi == 2) ? 0 : bi + 1;
    }

    // Butterfly max over token rows (lane bits 2..4).
#pragma unroll
    for (int nt = 0; nt < 2; nt++)
#pragma unroll
        for (int j = 0; j < 2; j++) {
            float x = rmax[nt][j];
#pragma unroll
            for (int o = 4; o < 32; o <<= 1)
                x = fmaxf(x, __shfl_xor_sync(0xFFFFFFFFu, x, o));
            rmax[nt][j] = x;
        }

    // Warp covers 16 q-cols: local col = nt*8 + (lane&3)*2 + j.
    if (lid < 4) {
#pragma unroll
        for (int nt = 0; nt < 2; nt++)
#pragma unroll
            for (int j = 0; j < 2; j++)
                red[wid * 16 + nt * 8 + lid * 2 + j] = rmax[nt][j];
    }
    __syncthreads();

    // Final: combine the two m-tile warps per n-half, q-mask, sum over q.
    if (tid < 32) {
        const int h = tid >> 4;
        const int i = tid & 15;
        float m = fmaxf(red[(h * 2) * 16 + i], red[(h * 2 + 1) * 16 + i]);
        const int qok = qm[b * QQ + tid];
        float contrib = (qok != 0 && m != MASKV) ? m : 0.0f;
#pragma unroll
        for (int o = 16; o; o >>= 1)
            contrib += __shfl_xor_sync(0xFFFFFFFFu, contrib, o);
        if (tid == 0) out[doc] = contrib;
    }
}

extern "C" void kernel_launch(void* const* d_in, const int* in_sizes, int n_in,
                              void* d_out, int out_size) {
    (void)in_sizes; (void)n_in; (void)out_size;
    cudaFuncSetAttribute(mvr_maxsim_kernel,
                         cudaFuncAttributeMaxDynamicSharedMemorySize, SMEM_BYTES);
    mvr_maxsim_kernel<<<BB * NN, 128, SMEM_BYTES>>>(
        (const float*)d_in[0], (const int*)d_in[1],
        (const float*)d_in[2], (const int*)d_in[3],
        (float*)d_out);
}